// round 9
// baseline (speedup 1.0000x reference)
#include <cuda_runtime.h>

#define CCH 512
#define TT  8192
#define NC2 256              // channel pairs (c, c+256)
#define PLANE2 (TT * NC2)

typedef unsigned long long u64;

__device__ __forceinline__ u64 fma2(u64 a, u64 b, u64 c) {
    u64 d; asm("fma.rn.f32x2 %0, %1, %2, %3;" : "=l"(d) : "l"(a), "l"(b), "l"(c)); return d;
}
__device__ __forceinline__ u64 mul2(u64 a, u64 b) {
    u64 d; asm("mul.rn.f32x2 %0, %1, %2;" : "=l"(d) : "l"(a), "l"(b)); return d;
}
__device__ __forceinline__ u64 add2(u64 a, u64 b) {
    u64 d; asm("add.rn.f32x2 %0, %1, %2;" : "=l"(d) : "l"(a), "l"(b)); return d;
}
__device__ __forceinline__ u64 pack2(float lo, float hi) {
    u64 d; asm("mov.b64 %0, {%1, %2};" : "=l"(d) : "f"(lo), "f"(hi)); return d;
}
__device__ __forceinline__ float2 unpack2(u64 a) {
    float2 r; asm("mov.b64 {%0, %1}, %2;" : "=f"(r.x), "=f"(r.y) : "l"(a)); return r;
}

// ---- static device scratch ----
// Channel-pair planes: element [t*256+c2] packs (channel c2, channel c2+256).
__device__ ulonglong2 g_K01[PLANE2];   // {(k0A,k0B),(k1A,k1B)}
__device__ ulonglong2 g_K23[PLANE2];   // {(k2A,k2B),(k3A,k3B)}
__device__ ulonglong2 g_V01[PLANE2];
__device__ ulonglong2 g_V23[PLANE2];
__device__ ulonglong2 g_KV4[PLANE2];   // {(k4A,k4B),(v4A,v4B)}
__device__ float g_U[TT * 16];         // U[t,j]
__device__ float g_invd[TT];
__device__ u64   g_dotT[PLANE2];       // (dotA, dotB) per [t][c2]

// ---------------- repack K,V ----------------
__global__ void repack_kv(const float* __restrict__ K, const float* __restrict__ V)
{
    const int idx = blockIdx.x * blockDim.x + threadIdx.x;   // t*256 + c2
    const int t  = idx >> 8;
    const int c2 = idx & 255;
    const long bA = ((long)t * CCH + c2) * 5;
    const long bB = ((long)t * CCH + c2 + 256) * 5;
    ulonglong2 r;
    r.x = pack2(K[bA + 0], K[bB + 0]); r.y = pack2(K[bA + 1], K[bB + 1]);
    g_K01[idx] = r;
    r.x = pack2(K[bA + 2], K[bB + 2]); r.y = pack2(K[bA + 3], K[bB + 3]);
    g_K23[idx] = r;
    r.x = pack2(V[bA + 0], V[bB + 0]); r.y = pack2(V[bA + 1], V[bB + 1]);
    g_V01[idx] = r;
    r.x = pack2(V[bA + 2], V[bB + 2]); r.y = pack2(V[bA + 3], V[bB + 3]);
    g_V23[idx] = r;
    r.x = pack2(K[bA + 4], K[bB + 4]); r.y = pack2(V[bA + 4], V[bB + 4]);
    g_KV4[idx] = r;
}

// ---------------- precompute U ----------------
__global__ void precompute_U(const float* __restrict__ y,
                             const float* __restrict__ W1,
                             const float* __restrict__ b1)
{
    const int j  = threadIdx.x & 15;
    const int t4 = blockIdx.x * 32 + (threadIdx.x >> 4);
    const int t0 = t4 * 4;
    const float bj = b1[j];
    float a0 = bj, a1 = bj, a2 = bj, a3 = bj;
#pragma unroll 8
    for (int c = 0; c < CCH; c++) {
        const float4 yv = *(const float4*)&y[c * TT + t0];
        const float w = W1[c * 16 + j];
        a0 = fmaf(yv.x, w, a0);
        a1 = fmaf(yv.y, w, a1);
        a2 = fmaf(yv.z, w, a2);
        a3 = fmaf(yv.w, w, a3);
    }
    g_U[(t0 + 0) * 16 + j] = a0;
    g_U[(t0 + 1) * 16 + j] = a1;
    g_U[(t0 + 2) * 16 + j] = a2;
    g_U[(t0 + 3) * 16 + j] = a3;
}

// ---------------- sequential recurrence, 1 CTA, 256 threads ----------------
__global__ __launch_bounds__(256, 1)
void rca_kernel(const float* __restrict__ W1,
                const float* __restrict__ W2,
                const float* __restrict__ b2)
{
    __shared__ __align__(16) u64 sdot[NC2];   // (dotA(c2), dotB(c2+256))
    __shared__ __align__(16) u64 sh2[16];     // (h_j, h_j) duplicated
    __shared__ float ss[8];

    const int tid  = threadIdx.x;
    const int wid  = tid >> 5;
    const int lane = tid & 31;
    const int jA = wid, jB = wid + 8;

    // B-phase weights: lane covers c2 in {2l+64ii, 2l+64ii+1}, channels c2 / c2+256
    float w1A[16], w1B[16];
#pragma unroll
    for (int ii = 0; ii < 4; ii++) {
        const int c2 = 2 * lane + 64 * ii;
        w1A[ii * 4 + 0] = W1[c2 * 16 + jA];
        w1A[ii * 4 + 1] = W1[(c2 + 256) * 16 + jA];
        w1A[ii * 4 + 2] = W1[(c2 + 1) * 16 + jA];
        w1A[ii * 4 + 3] = W1[(c2 + 257) * 16 + jA];
        w1B[ii * 4 + 0] = W1[c2 * 16 + jB];
        w1B[ii * 4 + 1] = W1[(c2 + 256) * 16 + jB];
        w1B[ii * 4 + 2] = W1[(c2 + 1) * 16 + jB];
        w1B[ii * 4 + 3] = W1[(c2 + 257) * 16 + jB];
    }

    // C-phase weights packed per channel pair
    u64 w2r[16];
#pragma unroll
    for (int j = 0; j < 16; j++)
        w2r[j] = pack2(W2[j * CCH + tid], W2[j * CCH + tid + 256]);
    const u64 b2c2 = pack2(b2[tid], b2[tid + 256]);

    const u64 c95 = pack2(0.95f, 0.95f);
    const u64 c05 = pack2(0.05f, 0.05f);
    u64 e0 = 0, e1 = 0, e2 = 0, e3 = 0, e4 = 0;

    // depth-2 prefetch
    ulonglong2 k01[2], k23[2], v01[2], v23[2], kv4[2];
    float uA[2], uB[2];
#pragma unroll
    for (int i = 0; i < 2; i++) {
        const int idx = i * NC2 + tid;
        k01[i] = g_K01[idx]; k23[i] = g_K23[idx];
        v01[i] = g_V01[idx]; v23[i] = g_V23[idx];
        kv4[i] = g_KV4[idx];
        uA[i] = g_U[i * 16 + wid];
        uB[i] = g_U[i * 16 + wid + 8];
    }

    sdot[tid] = 0;
    if (tid < 8) ss[tid] = 0.f;
    __syncthreads();

    const float4* sd4 = (const float4*)sdot;
    const ulonglong2* sh4 = (const ulonglong2*)sh2;

    for (int t0 = 0; t0 < TT + 2; t0 += 2) {
#pragma unroll
        for (int i = 0; i < 2; i++) {
            const int t = t0 + i;

            // ---------- B: gA=sum dot*W1[:,jA], gB=..., s=sum ema^2 ----------
            float gA0 = 0.f, gA1 = 0.f, gB0 = 0.f, gB1 = 0.f;
#pragma unroll
            for (int ii = 0; ii < 4; ii++) {
                const float4 d = sd4[lane + 32 * ii];
                gA0 = fmaf(d.x, w1A[ii * 4 + 0], gA0);
                gA1 = fmaf(d.y, w1A[ii * 4 + 1], gA1);
                gA0 = fmaf(d.z, w1A[ii * 4 + 2], gA0);
                gA1 = fmaf(d.w, w1A[ii * 4 + 3], gA1);
                gB0 = fmaf(d.x, w1B[ii * 4 + 0], gB0);
                gB1 = fmaf(d.y, w1B[ii * 4 + 1], gB1);
                gB0 = fmaf(d.z, w1B[ii * 4 + 2], gB0);
                gB1 = fmaf(d.w, w1B[ii * 4 + 3], gB1);
            }
            float gA = gA0 + gA1, gB = gB0 + gB1;
            float s = ss[lane & 7];
            // interleaved chains: gA(5), gB(5), s(3)
            gA += __shfl_xor_sync(0xffffffffu, gA, 16);
            gB += __shfl_xor_sync(0xffffffffu, gB, 16);
            s  += __shfl_xor_sync(0xffffffffu, s, 4);
            gA += __shfl_xor_sync(0xffffffffu, gA, 8);
            gB += __shfl_xor_sync(0xffffffffu, gB, 8);
            s  += __shfl_xor_sync(0xffffffffu, s, 2);
            gA += __shfl_xor_sync(0xffffffffu, gA, 4);
            gB += __shfl_xor_sync(0xffffffffu, gB, 4);
            s  += __shfl_xor_sync(0xffffffffu, s, 1);
            gA += __shfl_xor_sync(0xffffffffu, gA, 2);
            gB += __shfl_xor_sync(0xffffffffu, gB, 2);
            gA += __shfl_xor_sync(0xffffffffu, gA, 1);
            gB += __shfl_xor_sync(0xffffffffu, gB, 1);

            const float inv = rsqrtf(fmaxf(s, 1e-37f));
            if (lane == 0) {
                const float hA = fmaxf(fmaf(gA, inv, uA[i]), 0.f);
                const float hB = fmaxf(fmaf(gB, inv, uB[i]), 0.f);
                sh2[jA] = pack2(hA, hA);
                sh2[jB] = pack2(hB, hB);
                if (wid == 0 && t > 0) g_invd[t - 1] = inv;
            }
            if (t == TT) return;

            __syncthreads();   // sh2 visible; sdot/ss reads done before A writes

            // ---------- C: q2 = (qA,qB) = b2 + sum_j h_j * W2[j,(cA,cB)] ----------
            u64 q0 = b2c2, q1 = 0, q2a = 0, q3 = 0;
#pragma unroll
            for (int jj = 0; jj < 8; jj += 2) {
                const ulonglong2 hp0 = sh4[jj];
                const ulonglong2 hp1 = sh4[jj + 1];
                q0  = fma2(hp0.x, w2r[2 * jj + 0], q0);
                q1  = fma2(hp0.y, w2r[2 * jj + 1], q1);
                q2a = fma2(hp1.x, w2r[2 * jj + 2], q2a);
                q3  = fma2(hp1.y, w2r[2 * jj + 3], q3);
            }
            const u64 qm2 = mul2(add2(add2(q0, q1), add2(q2a, q3)), c05);

            // ---------- A: packed ema, dot, sp ----------
            e0 = fma2(e0, c95, mul2(k01[i].x, qm2));
            e1 = fma2(e1, c95, mul2(k01[i].y, qm2));
            e2 = fma2(e2, c95, mul2(k23[i].x, qm2));
            e3 = fma2(e3, c95, mul2(k23[i].y, qm2));
            e4 = fma2(e4, c95, mul2(kv4[i].x, qm2));

            u64 d2 = mul2(e0, v01[i].x);
            d2 = fma2(e1, v01[i].y, d2);
            d2 = fma2(e2, v23[i].x, d2);
            d2 = fma2(e3, v23[i].y, d2);
            d2 = fma2(e4, kv4[i].y, d2);

            u64 s2 = mul2(e0, e0);
            s2 = fma2(e1, e1, s2);
            s2 = fma2(e2, e2, s2);
            s2 = fma2(e3, e3, s2);
            s2 = fma2(e4, e4, s2);
            const float2 sv = unpack2(s2);
            float sp = sv.x + sv.y;

            sdot[tid] = d2;                 // (dotA, dotB)
            g_dotT[t * NC2 + tid] = d2;     // paired coalesced store

            // prefetch t+2 into this slot
            {
                const int tn  = (t + 2 < TT) ? (t + 2) : (TT - 1);
                const int idx = tn * NC2 + tid;
                k01[i] = g_K01[idx]; k23[i] = g_K23[idx];
                v01[i] = g_V01[idx]; v23[i] = g_V23[idx];
                kv4[i] = g_KV4[idx];
                uA[i] = g_U[tn * 16 + wid];
                uB[i] = g_U[tn * 16 + wid + 8];
            }

            // sp chain -> ss[wid]
            sp += __shfl_xor_sync(0xffffffffu, sp, 16);
            sp += __shfl_xor_sync(0xffffffffu, sp, 8);
            sp += __shfl_xor_sync(0xffffffffu, sp, 4);
            sp += __shfl_xor_sync(0xffffffffu, sp, 2);
            sp += __shfl_xor_sync(0xffffffffu, sp, 1);
            if (lane == 0) ss[wid] = sp;

            __syncthreads();   // sdot/ss visible for next B
        }
    }
}

// ---------------- transpose + scale ----------------
// float view of g_dotT: channel c at [t*512 + 2*(c&255) + (c>>8)]
__global__ void transpose_scale(float* __restrict__ out)
{
    __shared__ float tile[32][33];
    const int t0 = blockIdx.x * 32;
    const int c0 = blockIdx.y * 32;
    const int tx = threadIdx.x;
    const int ty = threadIdx.y;
    const float* gf = (const float*)g_dotT;
    const int half = c0 >> 8;            // uniform per block (32 | 256)
    const int cm = (c0 & 255) + tx;

#pragma unroll
    for (int r = ty; r < 32; r += 8)
        tile[r][tx] = gf[(t0 + r) * CCH + 2 * cm + half] * g_invd[t0 + r];
    __syncthreads();
#pragma unroll
    for (int r = ty; r < 32; r += 8)
        out[(long)(c0 + r) * TT + (t0 + tx)] = tile[tx][r];
}

extern "C" void kernel_launch(void* const* d_in, const int* in_sizes, int n_in,
                              void* d_out, int out_size) {
    const float* y  = (const float*)d_in[0];
    const float* Kp = (const float*)d_in[1];
    const float* Vp = (const float*)d_in[2];
    const float* W1 = (const float*)d_in[3];
    const float* b1 = (const float*)d_in[4];
    const float* W2 = (const float*)d_in[5];
    const float* b2 = (const float*)d_in[6];
    float* out = (float*)d_out;

    repack_kv<<<PLANE2 / 256, 256>>>(Kp, Vp);
    precompute_U<<<TT / 128, 512>>>(y, W1, b1);
    rca_kernel<<<1, 256>>>(W1, W2, b2);
    dim3 tb(32, 8);
    dim3 tg(TT / 32, CCH / 32);
    transpose_scale<<<tg, tb>>>(out);
}